// round 6
// baseline (speedup 1.0000x reference)
#include <cuda_runtime.h>
#include <cuda_fp16.h>

#define B_   4
#define CIN  256
#define CO_  64
#define N_   576   // 24*24
#define CV_  256

// Scratch (device globals — no allocation allowed)
__device__ unsigned g_kph[B_ * N_ * 32];       // (B, Nk, 32) half2 pairs over c
__device__ unsigned g_qph[B_ * N_ * 32];       // (B, Nq, 32)
__device__ float    g_attn[B_ * N_ * N_];      // (B, Nk, Nq)

// ---------- packed helpers ----------
__device__ __forceinline__ unsigned long long pack2(float lo, float hi) {
    unsigned long long r;
    asm("mov.b64 %0, {%1, %2};" : "=l"(r) : "f"(lo), "f"(hi));
    return r;
}
__device__ __forceinline__ void unpack2(unsigned long long v, float& lo, float& hi) {
    asm("mov.b64 {%0, %1}, %2;" : "=f"(lo), "=f"(hi) : "l"(v));
}
__device__ __forceinline__ unsigned long long ffma2(unsigned long long a,
                                                    unsigned long long b,
                                                    unsigned long long c) {
    unsigned long long d;
    asm("fma.rn.f32x2 %0, %1, %2, %3;" : "=l"(d) : "l"(a), "l"(b), "l"(c));
    return d;
}
__device__ __forceinline__ float tanhfast(float x) {
    float y;
    asm("tanh.approx.f32 %0, %1;" : "=f"(y) : "f"(x));
    return y;
}
__device__ __forceinline__ unsigned tanh_h2(unsigned x) {
    unsigned y;
    asm("tanh.approx.f16x2 %0, %1;" : "=r"(y) : "r"(x));
    return y;
}
__device__ __forceinline__ __half2 u2h(unsigned u) { return *(__half2*)&u; }
__device__ __forceinline__ unsigned h2u(__half2 h) { return *(unsigned*)&h; }

// ============================================================================
// Kernel A: projections. outh2[b,n,cc] = half2(sum_ch X*W + b)[c=2cc, 2cc+1]
// grid (18 n-tiles of 32, B, 2), 512 thr (16 warps/SM, 4/SMSP).
// Full-K staging (X 32KB + W 67.6KB), ONE barrier, thread = 2c x 2n.
// ============================================================================
#define PROJ_SMEM_BYTES ((256 * 32 + 256 * 66) * 4)

__global__ void __launch_bounds__(512) proj_kernel(
    const float* __restrict__ key, const float* __restrict__ query,
    const float* __restrict__ Wk,  const float* __restrict__ bk,
    const float* __restrict__ Wq,  const float* __restrict__ bq)
{
    extern __shared__ float smem[];
    float (*sX)[32] = (float (*)[32])smem;               // [256 ch][32 n]
    float (*sW)[66] = (float (*)[66])(smem + 256 * 32);  // [256 ch][64 c]

    const int kind = blockIdx.z;
    const float* X    = kind ? query : key;    // (B, CIN, N)
    const float* W    = kind ? Wq    : Wk;     // (CO, CIN)
    const float* bias = kind ? bq    : bk;
    unsigned* outp    = kind ? g_qph : g_kph;  // (B, N, 32) half2

    const int b  = blockIdx.y;
    const int n0 = blockIdx.x * 32;
    const int t  = threadIdx.x;

    // ---- stage X: 256ch x 32n as float4 (coalesced; 4 LDG.128/thread) ----
    {
        const int n4  = (t & 7) * 4;
        const int chb = t >> 3;                  // 0..63
        #pragma unroll
        for (int i = 0; i < 4; i++) {
            const int ch = chb + i * 64;
            *(float4*)&sX[ch][n4] =
                *(const float4*)&X[((size_t)(b * CIN + ch)) * N_ + n0 + n4];
        }
    }
    // ---- stage W transposed: sW[ch][c] (coalesced LDG over ch) ----
    {
        const int ch = t & 255;
        const int cb = (t >> 8) * 32;            // 0 or 32
        #pragma unroll 8
        for (int j = 0; j < 32; j++) {
            const int cr = cb + j;
            sW[ch][cr] = W[cr * CIN + ch];
        }
    }
    __syncthreads();

    // ---- compute: thread = 2c x 2n ----
    const int ng = t & 15;           // n = 2*ng, 2*ng+1
    const int c  = (t >> 4) * 2;     // c, c+1

    unsigned long long a0 = 0ull, a1 = 0ull;   // (n-pair) for c and c+1

    #pragma unroll 8
    for (int ch = 0; ch < CIN; ch++) {
        const unsigned long long xp = *(const unsigned long long*)&sX[ch][ng * 2];
        const float2 w2 = *(const float2*)&sW[ch][c];
        a0 = ffma2(xp, pack2(w2.x, w2.x), a0);
        a1 = ffma2(xp, pack2(w2.y, w2.y), a1);
    }

    const float bv0 = bias[c];
    const float bv1 = bias[c + 1];
    float c0n0, c0n1, c1n0, c1n1;
    unpack2(a0, c0n0, c0n1);
    unpack2(a1, c1n0, c1n1);

    const int n  = n0 + ng * 2;
    const int cc = c >> 1;
    outp[((size_t)b * N_ + n + 0) * 32 + cc] =
        h2u(__floats2half2_rn(c0n0 + bv0, c1n0 + bv1));
    outp[((size_t)b * N_ + n + 1) * 32 + cc] =
        h2u(__floats2half2_rn(c0n1 + bv0, c1n1 + bv1));
}

// ============================================================================
// Kernel B: attn[b,k,q] = sigmoid( bf + sum_c tanh(kp[k,c]+qp[q,c])*wf[c] )
// grid (18 q-tiles, 18 k-tiles, B), 256 thr. Thread = 4k x 1q (q = lane).
// Staging is pure uint2 copies (proj already emitted half2).
// ============================================================================
__global__ void __launch_bounds__(256) attn_kernel(
    const float* __restrict__ wf, const float* __restrict__ bfp)
{
    const int b  = blockIdx.z;
    const int k0 = blockIdx.y * 32;
    const int q0 = blockIdx.x * 32;

    __shared__ unsigned skh[32][34];   // half2 pairs over c
    __shared__ unsigned sqh[32][34];
    __shared__ unsigned swh[32];

    const int t = threadIdx.x;
    #pragma unroll
    for (int j = 0; j < 2; j++) {
        const int idx = t + j * 256;       // 512 uint2 per tile side
        const int r = idx >> 4;            // 0..31
        const int u = idx & 15;            // uint2 column
        *(uint2*)&skh[r][u * 2] =
            *(const uint2*)&g_kph[((size_t)b * N_ + k0 + r) * 32 + u * 2];
        *(uint2*)&sqh[r][u * 2] =
            *(const uint2*)&g_qph[((size_t)b * N_ + q0 + r) * 32 + u * 2];
    }
    if (t < 32) {
        const float2 w = *(const float2*)&wf[t * 2];
        swh[t] = h2u(__floats2half2_rn(w.x, w.y));
    }
    __syncthreads();

    const int q  = t & 31;            // lane -> CF q loads, coalesced STG
    const int k4 = (t >> 5) * 4;      // 4 k's (warp-constant -> broadcast)

    __half2 ae[4], ao[4];
    #pragma unroll
    for (int i = 0; i < 4; i++) { ae[i] = __float2half2_rn(0.f); ao[i] = ae[i]; }

    const unsigned* __restrict__ qrow = sqh[q];

    #pragma unroll
    for (int cc = 0; cc < 32; cc += 2) {
        const uint2 qv = *(const uint2*)&qrow[cc];
        const uint2 wv = *(const uint2*)&swh[cc];
        #pragma unroll
        for (int i = 0; i < 4; i++) {
            const uint2 kv = *(const uint2*)&skh[k4 + i][cc];
            const unsigned t0 = tanh_h2(h2u(__hadd2(u2h(kv.x), u2h(qv.x))));
            const unsigned t1 = tanh_h2(h2u(__hadd2(u2h(kv.y), u2h(qv.y))));
            ae[i] = __hfma2(u2h(t0), u2h(wv.x), ae[i]);
            ao[i] = __hfma2(u2h(t1), u2h(wv.y), ao[i]);
        }
    }

    const float bf = __ldg(bfp);
    #pragma unroll
    for (int i = 0; i < 4; i++) {
        const float2 fe = __half22float2(ae[i]);
        const float2 fo = __half22float2(ao[i]);
        const float s = bf + ((fe.x + fe.y) + (fo.x + fo.y));
        g_attn[((size_t)b * N_ + k0 + k4 + i) * N_ + q0 + q] =
            fmaf(0.5f, tanhfast(0.5f * s), 0.5f);   // sigmoid
    }
}

// ============================================================================
// Kernel C: out[b,c,q] = sum_k value[b,c,k] * attn[b,k,q]
// grid (9 q-tiles of 64, 4 c-tiles of 64, B), 256 thr; thread = 4c x 4q.
// (unchanged)
// ============================================================================
__global__ void __launch_bounds__(256) out_kernel(
    const float* __restrict__ value, float* __restrict__ out)
{
    const int b  = blockIdx.z;
    const int c0 = blockIdx.y * 64;
    const int q0 = blockIdx.x * 64;

    __shared__ __align__(16) float sV[32][68];   // [k][c]
    __shared__ __align__(16) float sA[32][68];   // [k][q]

    const int t  = threadIdx.x;
    const int qg = t & 15;          // q = qg*4 .. +3
    const int cg = t >> 4;          // c = cg*4 .. +3

    unsigned long long acc[4][2];
    #pragma unroll
    for (int i = 0; i < 4; i++) { acc[i][0] = 0ull; acc[i][1] = 0ull; }

    for (int k0 = 0; k0 < N_; k0 += 32) {
        {   // V tile 64c x 32k, transpose into sV[k][c] (coalesced over k)
            const int kk = t & 31;
            const int cb = t >> 5;
            #pragma unroll
            for (int i = 0; i < 8; i++) {
                const int cr = cb + i * 8;
                sV[kk][cr] = value[((size_t)(b * CV_ + c0 + cr)) * N_ + k0 + kk];
            }
        }
        {   // A tile 32k x 64q (coalesced over q)
            const int q  = t & 63;
            const int kb = t >> 6;
            #pragma unroll
            for (int i = 0; i < 8; i++) {
                const int kr = kb + i * 4;
                sA[kr][q] = g_attn[((size_t)b * N_ + k0 + kr) * N_ + q0 + q];
            }
        }
        __syncthreads();

        #pragma unroll 8
        for (int kk = 0; kk < 32; kk++) {
            const float4 v4 = *(const float4*)&sV[kk][cg * 4];         // 4 c
            const ulonglong2 a2 = *(const ulonglong2*)&sA[kk][qg * 4]; // 4 q
            const unsigned long long v0 = pack2(v4.x, v4.x);
            const unsigned long long v1 = pack2(v4.y, v4.y);
            const unsigned long long v2 = pack2(v4.z, v4.z);
            const unsigned long long v3 = pack2(v4.w, v4.w);
            acc[0][0] = ffma2(v0, a2.x, acc[0][0]);
            acc[0][1] = ffma2(v0, a2.y, acc[0][1]);
            acc[1][0] = ffma2(v1, a2.x, acc[1][0]);
            acc[1][1] = ffma2(v1, a2.y, acc[1][1]);
            acc[2][0] = ffma2(v2, a2.x, acc[2][0]);
            acc[2][1] = ffma2(v2, a2.y, acc[2][1]);
            acc[3][0] = ffma2(v3, a2.x, acc[3][0]);
            acc[3][1] = ffma2(v3, a2.y, acc[3][1]);
        }
        __syncthreads();
    }

    #pragma unroll
    for (int i = 0; i < 4; i++) {
        float o0, o1, o2, o3;
        unpack2(acc[i][0], o0, o1);
        unpack2(acc[i][1], o2, o3);
        *(float4*)&out[((size_t)(b * CV_ + c0 + cg * 4 + i)) * N_ + q0 + qg * 4] =
            make_float4(o0, o1, o2, o3);
    }
}

// ============================================================================
extern "C" void kernel_launch(void* const* d_in, const int* in_sizes, int n_in,
                              void* d_out, int out_size)
{
    const float* key   = (const float*)d_in[0];
    const float* query = (const float*)d_in[1];
    const float* value = (const float*)d_in[2];
    const float* Wk    = (const float*)d_in[3];
    const float* bk    = (const float*)d_in[4];
    const float* Wq    = (const float*)d_in[5];
    const float* bq    = (const float*)d_in[6];
    const float* wf    = (const float*)d_in[7];
    const float* bf    = (const float*)d_in[8];
    float* out = (float*)d_out;

    static int smem_set = 0;
    if (!smem_set) {
        cudaFuncSetAttribute(proj_kernel,
                             cudaFuncAttributeMaxDynamicSharedMemorySize,
                             PROJ_SMEM_BYTES);
        smem_set = 1;
    }

    proj_kernel<<<dim3(N_ / 32, B_, 2), 512, PROJ_SMEM_BYTES>>>(key, query, Wk, bk, Wq, bq);
    attn_kernel<<<dim3(N_ / 32, N_ / 32, B_), 256>>>(wf, bf);
    out_kernel<<<dim3(N_ / 64, CV_ / 64, B_), 256>>>(value, out);
}